// round 7
// baseline (speedup 1.0000x reference)
#include <cuda_runtime.h>
#include <cuda_fp16.h>

typedef unsigned long long u64;

#define NN     50000
#define EE     800000
#define HH     2
#define DD     32
#define HD     64
#define INDIM  64
#define ERELN  200000
#define DRELN  32

// ---------------- scratch ----------------
__device__ u64      g_hph8[NN * 16];       // half hp   (edge gather + residual)
__device__ u64      g_vmidh8[NN * 16];     // half vmid (edge gather)
__device__ u64      g_vrelh8[ERELN * 16];  // half vrel (edge gather)
__device__ float2   g_es2[NN];
__device__ float2   g_ed2[NN];
__device__ float2   g_sm2[NN];
__device__ float2   g_sr2[ERELN];
__device__ float2   g_denom2[NN];
__device__ float4   g_rst4[NN * 16];
__device__ float    g_Mmid[INDIM * HD];
__device__ float    g_Mrel[DRELN * HD];
__device__ float    g_vb[HD];

// ---------------- helpers ----------------
__device__ __forceinline__ u64 pack2(float lo, float hi) {
    u64 r; asm("mov.b64 %0, {%1,%2};" : "=l"(r) : "f"(lo), "f"(hi)); return r;
}
__device__ __forceinline__ void unpack2(u64 v, float& lo, float& hi) {
    asm("mov.b64 {%0,%1}, %2;" : "=f"(lo), "=f"(hi) : "l"(v));
}
__device__ __forceinline__ void ffma2(u64& d, u64 a, u64 b) {
    asm("fma.rn.f32x2 %0, %1, %2, %0;" : "+l"(d) : "l"(a), "l"(b));
}
__device__ __forceinline__ u64 addf32x2(u64 a, u64 b) {
    u64 r; asm("add.rn.f32x2 %0, %1, %2;" : "=l"(r) : "l"(a), "l"(b)); return r;
}
__device__ __forceinline__ void red_add_v4(float* p, float4 v) {
    asm volatile("red.global.add.v4.f32 [%0], {%1,%2,%3,%4};"
                 :: "l"(p), "f"(v.x), "f"(v.y), "f"(v.z), "f"(v.w) : "memory");
}
__device__ __forceinline__ void red_add_v2(float2* p, float a, float b) {
    asm volatile("red.global.add.v2.f32 [%0], {%1,%2};"
                 :: "l"(p), "f"(a), "f"(b) : "memory");
}

// ---------------- init + prep ----------------
__global__ void k_init_prep(const float* __restrict__ W_mid, const float* __restrict__ W_rel,
                            const float* __restrict__ b_mid, const float* __restrict__ b_rel,
                            const float* __restrict__ We) {
    int tid = threadIdx.x;
    if (blockIdx.x == 0) {
        __shared__ float sWe[64 * 32];
        for (int i = tid; i < 2048; i += 256) sWe[i] = We[i];
        __syncthreads();
        for (int idx = tid; idx < INDIM * HD; idx += 256) {
            int k = idx >> 6, c = idx & 63, h = c >> 5, d = c & 31;
            float acc = 0.f;
            for (int dd = 0; dd < 32; dd++)
                acc = fmaf(W_mid[k * 64 + h * 32 + dd], sWe[dd * 32 + d], acc);
            g_Mmid[idx] = acc;
        }
        for (int idx = tid; idx < DRELN * HD; idx += 256) {
            int k = idx >> 6, c = idx & 63, h = c >> 5, d = c & 31;
            float acc = 0.f;
            for (int dd = 0; dd < 32; dd++)
                acc = fmaf(W_rel[k * 64 + h * 32 + dd], sWe[(32 + dd) * 32 + d], acc);
            g_Mrel[idx] = acc;
        }
        if (tid < HD) {
            int h = tid >> 5, d = tid & 31;
            float acc = 0.f;
            for (int dd = 0; dd < 32; dd++) {
                acc = fmaf(b_mid[h * 32 + dd], sWe[dd * 32 + d], acc);
                acc = fmaf(b_rel[h * 32 + dd], sWe[(32 + dd) * 32 + d], acc);
            }
            g_vb[tid] = acc;
        }
    } else {
        int i = (blockIdx.x - 1) * 256 + tid;
        if (i < NN * 16) g_rst4[i] = make_float4(0.f, 0.f, 0.f, 0.f);
        if (i < NN)      g_denom2[i] = make_float2(0.f, 0.f);
    }
}

// ---------------- target projection: hp(half), e_src, e_dst ----------------
// 256 thr = 8 warps = 4 slots x 2 heads; 32 rows/block
__global__ void __launch_bounds__(256) k_proj_target(const float* __restrict__ x,
                              const float* __restrict__ W,
                              const float* __restrict__ b,
                              const float* __restrict__ asrc,
                              const float* __restrict__ adst) {
    __shared__ float sx[32 * INDIM];
    int tid = threadIdx.x, w = tid >> 5, lane = tid & 31;
    int slot = w >> 1, head = w & 1;
    int n0 = blockIdx.x * 32;
    int nrows = min(32, NN - n0);
    for (int i = tid; i < nrows * 16; i += 256)
        ((float4*)sx)[i] = ((const float4*)(x + (size_t)n0 * INDIM))[i];
    int col = head * 32 + lane;
    float wreg[INDIM];
#pragma unroll
    for (int k = 0; k < INDIM; k++) wreg[k] = W[k * HD + col];
    float bb = b[col];
    float as = asrc[col], ad = adst[col];
    __syncthreads();
    __half* hph = (__half*)g_hph8;
    for (int row = slot; row < nrows; row += 4) {
        int n = n0 + row;
        float a0 = bb, a1 = 0.f, a2 = 0.f, a3 = 0.f;
        const float4* xrw = (const float4*)(sx + row * INDIM);
#pragma unroll
        for (int k4 = 0; k4 < 16; k4++) {
            float4 xv = xrw[k4];
            a0 = fmaf(xv.x, wreg[4 * k4 + 0], a0);
            a1 = fmaf(xv.y, wreg[4 * k4 + 1], a1);
            a2 = fmaf(xv.z, wreg[4 * k4 + 2], a2);
            a3 = fmaf(xv.w, wreg[4 * k4 + 3], a3);
        }
        float acc = (a0 + a1) + (a2 + a3);
        hph[n * HD + col] = __float2half_rn(acc);
        float r = fmaxf(acc, 0.f);
        float vs = r * as, vd = r * ad;
#pragma unroll
        for (int o = 16; o > 0; o >>= 1) {
            vs += __shfl_down_sync(0xffffffffu, vs, o);
            vd += __shfl_down_sync(0xffffffffu, vd, o);
        }
        if (lane == 0) {
            ((float*)&g_es2[n])[head] = vs;
            ((float*)&g_ed2[n])[head] = vd;
        }
    }
}

// ---------------- mid projection: dup-x smem + FFMA2, K split across 2 warps ----------------
// 128 thr = 4 warps: head = w&1, kh = w>>1; 16 rows/block
__global__ void __launch_bounds__(128) k_proj_mid(const float* __restrict__ x,
                           const float* __restrict__ W,
                           const float* __restrict__ b,
                           const float* __restrict__ aedge) {
    __shared__ u64 sxd[16 * INDIM];   // (xk,xk) pairs, 8KB
    __shared__ u64 sp[2][16][64];     // partials, 16KB
    int tid = threadIdx.x, w = tid >> 5, lane = tid & 31;
    int head = w & 1, kh = w >> 1;
    int n0 = blockIdx.x * 16;
    {   // stage x duplicated: 256 float4 total, 2 per thread
        const float4* xs = (const float4*)(x + (size_t)n0 * INDIM);
        float4* sd = (float4*)sxd;
#pragma unroll
        for (int j = 0; j < 2; j++) {
            int i = tid + j * 128;
            float4 v = xs[i];
            int row = i >> 4, k0 = (i & 15) * 4;
            int o = row * 32 + (k0 >> 1);
            sd[o]     = make_float4(v.x, v.x, v.y, v.y);
            sd[o + 1] = make_float4(v.z, v.z, v.w, v.w);
        }
    }
    int col = head * 32 + lane;
    u64 wm[32];
#pragma unroll
    for (int kk = 0; kk < 32; kk++) {
        int k = kh * 32 + kk;
        wm[kk] = pack2(W[k * HD + col], g_Mmid[k * HD + col]);
    }
    __syncthreads();
    for (int row = 0; row < 16; row++) {
        u64 d0 = 0, d1 = 0, d2 = 0, d3 = 0;
        const u64* xd = sxd + row * INDIM + kh * 32;
#pragma unroll
        for (int k = 0; k < 32; k += 4) {
            ffma2(d0, xd[k + 0], wm[k + 0]);
            ffma2(d1, xd[k + 1], wm[k + 1]);
            ffma2(d2, xd[k + 2], wm[k + 2]);
            ffma2(d3, xd[k + 3], wm[k + 3]);
        }
        sp[kh][row][col] = addf32x2(addf32x2(d0, d1), addf32x2(d2, d3));
    }
    __syncthreads();
    if (kh == 0) {
        float bb = b[col];
        float av = aedge[head * 64 + lane];
        __half* vm = (__half*)g_vmidh8;
        for (int row = 0; row < 16; row++) {
            u64 p = addf32x2(sp[0][row][col], sp[1][row][col]);
            float acc, vacc; unpack2(p, acc, vacc);
            acc += bb;
            int n = n0 + row;
            vm[n * HD + col] = __float2half_rn(vacc);
            float s = fmaxf(acc, 0.f) * av;
#pragma unroll
            for (int o = 16; o > 0; o >>= 1) s += __shfl_down_sync(0xffffffffu, s, o);
            if (lane == 0) ((float*)&g_sm2[n])[head] = s;
        }
    }
}

// ---------------- rel projection: dup-x smem + FFMA2, K=32 in regs ----------------
// 128 thr = 4 warps = 2 slots x 2 heads; 32 rows/block
__global__ void __launch_bounds__(128) k_proj_rel(const float* __restrict__ x,
                           const float* __restrict__ W,
                           const float* __restrict__ b,
                           const float* __restrict__ aedge) {
    __shared__ u64 sxd[32 * DRELN];   // 8KB
    int tid = threadIdx.x, w = tid >> 5, lane = tid & 31;
    int slot = w >> 1, head = w & 1;
    int n0 = blockIdx.x * 32;
    {   // 256 float4, 2 per thread
        const float4* xs = (const float4*)(x + (size_t)n0 * DRELN);
        float4* sd = (float4*)sxd;
#pragma unroll
        for (int j = 0; j < 2; j++) {
            int i = tid + j * 128;
            float4 v = xs[i];
            int row = i >> 3, k0 = (i & 7) * 4;
            int o = row * 16 + (k0 >> 1);
            sd[o]     = make_float4(v.x, v.x, v.y, v.y);
            sd[o + 1] = make_float4(v.z, v.z, v.w, v.w);
        }
    }
    int col = head * 32 + lane;
    u64 wm[32];
#pragma unroll
    for (int k = 0; k < DRELN; k++)
        wm[k] = pack2(W[k * HD + col], g_Mrel[k * HD + col]);
    float bb = b[col];
    float av = aedge[head * 64 + 32 + lane];
    __syncthreads();
    __half* vr = (__half*)g_vrelh8;
    for (int row = slot; row < 32; row += 2) {
        int n = n0 + row;
        u64 d0 = 0, d1 = 0, d2 = 0, d3 = 0;
        const u64* xd = sxd + row * DRELN;
#pragma unroll
        for (int k = 0; k < 32; k += 4) {
            ffma2(d0, xd[k + 0], wm[k + 0]);
            ffma2(d1, xd[k + 1], wm[k + 1]);
            ffma2(d2, xd[k + 2], wm[k + 2]);
            ffma2(d3, xd[k + 3], wm[k + 3]);
        }
        float acc, vacc;
        unpack2(addf32x2(addf32x2(d0, d1), addf32x2(d2, d3)), acc, vacc);
        acc += bb;
        vr[n * HD + col] = __float2half_rn(vacc);
        float s = fmaxf(acc, 0.f) * av;
#pragma unroll
        for (int o = 16; o > 0; o >>= 1) s += __shfl_down_sync(0xffffffffu, s, o);
        if (lane == 0) ((float*)&g_sr2[n])[head] = s;
    }
}

// ---------------- fused edge pass: logits + exp + denom + weighted scatter ----------------
__global__ void k_edge_agg(const int* __restrict__ src, const int* __restrict__ dst,
                           const int* __restrict__ hn,  const int* __restrict__ he) {
    int gt = blockIdx.x * 256 + threadIdx.x;
    int e = gt >> 4;
    int q = gt & 15;
    int lane = threadIdx.x & 31;
    int s = src[e], t = dst[e], mn = hn[e], r = he[e];
    float ex0 = 0.f, ex1 = 0.f;
    if (q == 0) {
        float2 es = __ldg(&g_es2[s]);
        float2 ed = __ldg(&g_ed2[t]);
        float2 sm = __ldg(&g_sm2[mn]);
        float2 sr = __ldg(&g_sr2[r]);
        ex0 = __expf(es.x + ed.x + sm.x + sr.x);
        ex1 = __expf(es.y + ed.y + sm.y + sr.y);
        red_add_v2(&g_denom2[t], ex0, ex1);
    }
    int base = lane & ~15;
    ex0 = __shfl_sync(0xffffffffu, ex0, base);
    ex1 = __shfl_sync(0xffffffffu, ex1, base);
    float ex = (q & 8) ? ex1 : ex0;
    u64 A = __ldg(&g_hph8[s * 16 + q]);
    u64 B = __ldg(&g_vmidh8[mn * 16 + q]);
    u64 C = __ldg(&g_vrelh8[r * 16 + q]);
    __half2 a01 = ((__half2*)&A)[0], a23 = ((__half2*)&A)[1];
    __half2 b01 = ((__half2*)&B)[0], b23 = ((__half2*)&B)[1];
    __half2 c01 = ((__half2*)&C)[0], c23 = ((__half2*)&C)[1];
    __half2 s01 = __hadd2(__hadd2(a01, b01), c01);
    __half2 s23 = __hadd2(__hadd2(a23, b23), c23);
    float2 f01 = __half22float2(s01);
    float2 f23 = __half22float2(s23);
    float4 v;
    v.x = ex * f01.x; v.y = ex * f01.y;
    v.z = ex * f23.x; v.w = ex * f23.y;
    red_add_v4(((float*)g_rst4) + (size_t)t * HD + q * 4, v);
}

// ---------------- final: /denom, +vb, +b_edge, residual(half hp), relu, L2-normalize ----------------
__global__ void k_final(const float* __restrict__ b_edge, float* __restrict__ out) {
    int tid = threadIdx.x;
    int nl  = tid >> 6, c = tid & 63;
    int n   = blockIdx.x * 4 + nl;
    int hd  = c >> 5, d = c & 31;
    float den = ((const float*)&g_denom2[n])[hd];
    float rst = (den > 0.f) ? ((float*)g_rst4)[n * HD + c] / den + g_vb[c] : 0.f;
    float hpv = __half2float(((const __half*)g_hph8)[n * HD + c]);
    float val = fmaxf(rst + b_edge[d] + hpv, 0.f);
    float ss  = val * val;
#pragma unroll
    for (int o = 16; o > 0; o >>= 1) ss += __shfl_down_sync(0xffffffffu, ss, o);
    __shared__ float sp[8];
    if ((tid & 31) == 0) sp[tid >> 5] = ss;
    __syncthreads();
    float tot  = sp[nl * 2] + sp[nl * 2 + 1];
    float norm = fmaxf(sqrtf(tot), 1e-12f);
    out[n * HD + c] = val / norm;
}

extern "C" void kernel_launch(void* const* d_in, const int* in_sizes, int n_in,
                              void* d_out, int out_size) {
    const float* h         = (const float*)d_in[0];
    const float* W_t       = (const float*)d_in[1];
    const float* b_t       = (const float*)d_in[2];
    const float* nfeat_mid = (const float*)d_in[3];
    const float* W_mid     = (const float*)d_in[4];
    const float* b_mid     = (const float*)d_in[5];
    const float* efeat_rel = (const float*)d_in[6];
    const float* W_rel     = (const float*)d_in[7];
    const float* b_rel     = (const float*)d_in[8];
    const float* attn_src  = (const float*)d_in[9];
    const float* attn_dst  = (const float*)d_in[10];
    const float* attn_edge = (const float*)d_in[11];
    const float* W_edge    = (const float*)d_in[12];
    const float* b_edge    = (const float*)d_in[13];
    const int*   src_idx   = (const int*)d_in[14];
    const int*   dst_idx   = (const int*)d_in[15];
    const int*   hn        = (const int*)d_in[16];
    const int*   he        = (const int*)d_in[17];
    float* out = (float*)d_out;

    k_init_prep<<<3126, 256>>>(W_mid, W_rel, b_mid, b_rel, W_edge);
    k_proj_target<<<(NN + 31) / 32, 256>>>(h, W_t, b_t, attn_src, attn_dst);
    k_proj_mid<<<NN / 16, 128>>>(nfeat_mid, W_mid, b_mid, attn_edge);
    k_proj_rel<<<ERELN / 32, 128>>>(efeat_rel, W_rel, b_rel, attn_edge);
    k_edge_agg<<<(EE * 16) / 256, 256>>>(src_idx, dst_idx, hn, he);
    k_final<<<NN / 4, 256>>>(b_edge, out);
}

// round 8
// speedup vs baseline: 1.1538x; 1.1538x over previous
#include <cuda_runtime.h>
#include <cuda_fp16.h>

typedef unsigned long long u64;

#define NN     50000
#define EE     800000
#define HH     2
#define DD     32
#define HD     64
#define INDIM  64
#define ERELN  200000
#define DRELN  32

// ---------------- scratch ----------------
__device__ u64      g_hph8[NN * 16];       // half hp (edge gather + residual)
__device__ u64      g_vmidh8[NN * 16];
__device__ u64      g_vrelh8[ERELN * 16];
__device__ float2   g_es2[NN];
__device__ float2   g_ed2[NN];
__device__ float2   g_sm2[NN];
__device__ float2   g_sr2[ERELN];
__device__ float2   g_denom2[NN];
__device__ float4   g_rst4[NN * 16];
__device__ float    g_Mmid[INDIM * HD];
__device__ float    g_Mrel[DRELN * HD];
__device__ float    g_vb[HD];

// ---------------- helpers ----------------
__device__ __forceinline__ u64 pack2(float lo, float hi) {
    u64 r; asm("mov.b64 %0, {%1,%2};" : "=l"(r) : "f"(lo), "f"(hi)); return r;
}
__device__ __forceinline__ void unpack2(u64 v, float& lo, float& hi) {
    asm("mov.b64 {%0,%1}, %2;" : "=f"(lo), "=f"(hi) : "l"(v));
}
__device__ __forceinline__ void ffma2(u64& d, u64 a, u64 b) {
    asm("fma.rn.f32x2 %0, %1, %2, %0;" : "+l"(d) : "l"(a), "l"(b));
}
__device__ __forceinline__ u64 addf32x2(u64 a, u64 b) {
    u64 r; asm("add.rn.f32x2 %0, %1, %2;" : "=l"(r) : "l"(a), "l"(b)); return r;
}
__device__ __forceinline__ void red_add_v4(float* p, float4 v) {
    asm volatile("red.global.add.v4.f32 [%0], {%1,%2,%3,%4};"
                 :: "l"(p), "f"(v.x), "f"(v.y), "f"(v.z), "f"(v.w) : "memory");
}
__device__ __forceinline__ void red_add_v2(float2* p, float a, float b) {
    asm volatile("red.global.add.v2.f32 [%0], {%1,%2};"
                 :: "l"(p), "f"(a), "f"(b) : "memory");
}

// ---------------- init + prep ----------------
__global__ void k_init_prep(const float* __restrict__ W_mid, const float* __restrict__ W_rel,
                            const float* __restrict__ b_mid, const float* __restrict__ b_rel,
                            const float* __restrict__ We) {
    int tid = threadIdx.x;
    if (blockIdx.x == 0) {
        __shared__ float sWe[64 * 32];
        for (int i = tid; i < 2048; i += 256) sWe[i] = We[i];
        __syncthreads();
        for (int idx = tid; idx < INDIM * HD; idx += 256) {
            int k = idx >> 6, c = idx & 63, h = c >> 5, d = c & 31;
            float acc = 0.f;
            for (int dd = 0; dd < 32; dd++)
                acc = fmaf(W_mid[k * 64 + h * 32 + dd], sWe[dd * 32 + d], acc);
            g_Mmid[idx] = acc;
        }
        for (int idx = tid; idx < DRELN * HD; idx += 256) {
            int k = idx >> 6, c = idx & 63, h = c >> 5, d = c & 31;
            float acc = 0.f;
            for (int dd = 0; dd < 32; dd++)
                acc = fmaf(W_rel[k * 64 + h * 32 + dd], sWe[(32 + dd) * 32 + d], acc);
            g_Mrel[idx] = acc;
        }
        if (tid < HD) {
            int h = tid >> 5, d = tid & 31;
            float acc = 0.f;
            for (int dd = 0; dd < 32; dd++) {
                acc = fmaf(b_mid[h * 32 + dd], sWe[dd * 32 + d], acc);
                acc = fmaf(b_rel[h * 32 + dd], sWe[(32 + dd) * 32 + d], acc);
            }
            g_vb[tid] = acc;
        }
    } else {
        int i = (blockIdx.x - 1) * 256 + tid;
        if (i < NN * 16) g_rst4[i] = make_float4(0.f, 0.f, 0.f, 0.f);
        if (i < NN)      g_denom2[i] = make_float2(0.f, 0.f);
    }
}

// ---------------- target projection: K-split across warps ----------------
// 256 thr = 8 warps: kh = w&1, head = (w>>1)&1, slot = w>>2; 32 rows/block
__global__ void __launch_bounds__(256) k_proj_target(const float* __restrict__ x,
                              const float* __restrict__ W,
                              const float* __restrict__ b,
                              const float* __restrict__ asrc,
                              const float* __restrict__ adst) {
    __shared__ float sx[32 * INDIM];      // 8KB
    __shared__ float spT[2][32][HD];      // 16KB partials
    int tid = threadIdx.x, w = tid >> 5, lane = tid & 31;
    int kh = w & 1, head = (w >> 1) & 1, slot = w >> 2;
    int n0 = blockIdx.x * 32;
    int nrows = min(32, NN - n0);
    for (int i = tid; i < nrows * 16; i += 256)
        ((float4*)sx)[i] = ((const float4*)(x + (size_t)n0 * INDIM))[i];
    int col = head * 32 + lane;
    float wreg[32];
#pragma unroll
    for (int kk = 0; kk < 32; kk++) wreg[kk] = W[(kh * 32 + kk) * HD + col];
    __syncthreads();
    for (int row = slot; row < nrows; row += 2) {
        float a0 = 0.f, a1 = 0.f, a2 = 0.f, a3 = 0.f;
        const float4* xrw = (const float4*)(sx + row * INDIM + kh * 32);
#pragma unroll
        for (int k4 = 0; k4 < 8; k4++) {
            float4 xv = xrw[k4];
            a0 = fmaf(xv.x, wreg[4 * k4 + 0], a0);
            a1 = fmaf(xv.y, wreg[4 * k4 + 1], a1);
            a2 = fmaf(xv.z, wreg[4 * k4 + 2], a2);
            a3 = fmaf(xv.w, wreg[4 * k4 + 3], a3);
        }
        spT[kh][row][col] = (a0 + a1) + (a2 + a3);
    }
    __syncthreads();
    if (kh == 0) {
        float bb = b[col];
        float as = asrc[col], ad = adst[col];
        __half* hph = (__half*)g_hph8;
        for (int row = slot; row < nrows; row += 2) {
            int n = n0 + row;
            float acc = spT[0][row][col] + spT[1][row][col] + bb;
            hph[n * HD + col] = __float2half_rn(acc);
            float r = fmaxf(acc, 0.f);
            float vs = r * as, vd = r * ad;
#pragma unroll
            for (int o = 16; o > 0; o >>= 1) {
                vs += __shfl_down_sync(0xffffffffu, vs, o);
                vd += __shfl_down_sync(0xffffffffu, vd, o);
            }
            if (lane == 0) {
                ((float*)&g_es2[n])[head] = vs;
                ((float*)&g_ed2[n])[head] = vd;
            }
        }
    }
}

// ---------------- mid projection (R5 proven version) ----------------
// 128 thr = 4 warps: head = w&1, kh = w>>1; 16 rows/block
__global__ void __launch_bounds__(128) k_proj_mid(const float* __restrict__ x,
                           const float* __restrict__ W,
                           const float* __restrict__ b,
                           const float* __restrict__ aedge) {
    __shared__ float sx[16 * INDIM];
    __shared__ u64 sp[2][16][64];
    int tid = threadIdx.x, w = tid >> 5, lane = tid & 31;
    int head = w & 1, kh = w >> 1;
    int n0 = blockIdx.x * 16;
    {
        const float4* xs = (const float4*)(x + (size_t)n0 * INDIM);
        float4* sx4 = (float4*)sx;
        sx4[tid] = xs[tid];
        sx4[tid + 128] = xs[tid + 128];
    }
    int col = head * 32 + lane;
    u64 wm[32];
#pragma unroll
    for (int kk = 0; kk < 32; kk++) {
        int k = kh * 32 + kk;
        wm[kk] = pack2(W[k * HD + col], g_Mmid[k * HD + col]);
    }
    __syncthreads();
    for (int row = 0; row < 16; row++) {
        u64 d0 = 0, d1 = 0, d2 = 0, d3 = 0;
        const float4* xrw = (const float4*)(sx + row * INDIM + kh * 32);
#pragma unroll
        for (int k8 = 0; k8 < 4; k8++) {
            float4 xa = xrw[2 * k8], xb = xrw[2 * k8 + 1];
            ffma2(d0, pack2(xa.x, xa.x), wm[8 * k8 + 0]);
            ffma2(d1, pack2(xa.y, xa.y), wm[8 * k8 + 1]);
            ffma2(d2, pack2(xa.z, xa.z), wm[8 * k8 + 2]);
            ffma2(d3, pack2(xa.w, xa.w), wm[8 * k8 + 3]);
            ffma2(d0, pack2(xb.x, xb.x), wm[8 * k8 + 4]);
            ffma2(d1, pack2(xb.y, xb.y), wm[8 * k8 + 5]);
            ffma2(d2, pack2(xb.z, xb.z), wm[8 * k8 + 6]);
            ffma2(d3, pack2(xb.w, xb.w), wm[8 * k8 + 7]);
        }
        sp[kh][row][col] = addf32x2(addf32x2(d0, d1), addf32x2(d2, d3));
    }
    __syncthreads();
    if (kh == 0) {
        float bb = b[col];
        float av = aedge[head * 64 + lane];
        __half* vm = (__half*)g_vmidh8;
        for (int row = 0; row < 16; row++) {
            u64 p = addf32x2(sp[0][row][col], sp[1][row][col]);
            float acc, vacc; unpack2(p, acc, vacc);
            acc += bb;
            int n = n0 + row;
            vm[n * HD + col] = __float2half_rn(vacc);
            float s = fmaxf(acc, 0.f) * av;
#pragma unroll
            for (int o = 16; o > 0; o >>= 1) s += __shfl_down_sync(0xffffffffu, s, o);
            if (lane == 0) ((float*)&g_sm2[n])[head] = s;
        }
    }
}

// ---------------- rel projection: paired-rows FFMA2, K split across 2 warps ----------------
// 128 thr = 4 warps: kh = w&1, head = w>>1; 16 rows (8 pairs)/block
__global__ void __launch_bounds__(128) k_proj_rel(const float* __restrict__ x,
                           const float* __restrict__ W,
                           const float* __restrict__ b,
                           const float* __restrict__ aedge) {
    __shared__ u64 spx[8][DRELN];       // (xA[k],xB[k]) pairs, 2KB
    __shared__ u64 spW[2][8][64];       // 8KB
    __shared__ u64 spM[2][8][64];       // 8KB
    int tid = threadIdx.x, w = tid >> 5, lane = tid & 31;
    int kh = w & 1, head = w >> 1;
    int n0 = blockIdx.x * 16;
    {   // stage interleaved row pairs
        int row = tid >> 3, k4 = tid & 7;
        float4 v = ((const float4*)(x + (size_t)(n0 + row) * DRELN))[k4];
        int pair = row >> 1, sub = row & 1;
        float* bp = (float*)&spx[pair][k4 * 4];
        bp[0 + sub] = v.x; bp[2 + sub] = v.y;
        bp[4 + sub] = v.z; bp[6 + sub] = v.w;
    }
    int col = head * 32 + lane;
    u64 wdup[16], mdup[16];
#pragma unroll
    for (int kk = 0; kk < 16; kk++) {
        int k = kh * 16 + kk;
        float wv = W[k * HD + col];
        float mv = g_Mrel[k * HD + col];
        wdup[kk] = pack2(wv, wv);
        mdup[kk] = pack2(mv, mv);
    }
    __syncthreads();
#pragma unroll
    for (int p0 = 0; p0 < 4; p0++) {
        u64 dW0 = 0, dM0 = 0, dW1 = 0, dM1 = 0;
        const u64* xa = &spx[p0][kh * 16];
        const u64* xb = &spx[p0 + 4][kh * 16];
#pragma unroll
        for (int kk = 0; kk < 16; kk++) {
            u64 sa = xa[kk], sb = xb[kk];
            ffma2(dW0, sa, wdup[kk]);
            ffma2(dM0, sa, mdup[kk]);
            ffma2(dW1, sb, wdup[kk]);
            ffma2(dM1, sb, mdup[kk]);
        }
        spW[kh][p0][col] = dW0;  spM[kh][p0][col] = dM0;
        spW[kh][p0 + 4][col] = dW1;  spM[kh][p0 + 4][col] = dM1;
    }
    __syncthreads();
    if (kh == 0) {
        float bb = b[col];
        float av = aedge[head * 64 + 32 + lane];
        __half* vr = (__half*)g_vrelh8;
#pragma unroll
        for (int p = 0; p < 8; p++) {
            u64 uW = addf32x2(spW[0][p][col], spW[1][p][col]);
            u64 uM = addf32x2(spM[0][p][col], spM[1][p][col]);
            float aA, aB, vA, vB;
            unpack2(uW, aA, aB); unpack2(uM, vA, vB);
            aA += bb; aB += bb;
            int nA = n0 + 2 * p, nB = nA + 1;
            vr[nA * HD + col] = __float2half_rn(vA);
            vr[nB * HD + col] = __float2half_rn(vB);
            float sA = fmaxf(aA, 0.f) * av;
            float sB = fmaxf(aB, 0.f) * av;
#pragma unroll
            for (int o = 16; o > 0; o >>= 1) {
                sA += __shfl_down_sync(0xffffffffu, sA, o);
                sB += __shfl_down_sync(0xffffffffu, sB, o);
            }
            if (lane == 0) {
                ((float*)&g_sr2[nA])[head] = sA;
                ((float*)&g_sr2[nB])[head] = sB;
            }
        }
    }
}

// ---------------- fused edge pass (fp16 gathers) ----------------
__global__ void k_edge_agg(const int* __restrict__ src, const int* __restrict__ dst,
                           const int* __restrict__ hn,  const int* __restrict__ he) {
    int gt = blockIdx.x * 256 + threadIdx.x;
    int e = gt >> 4;
    int q = gt & 15;
    int lane = threadIdx.x & 31;
    int s = src[e], t = dst[e], mn = hn[e], r = he[e];
    float ex0 = 0.f, ex1 = 0.f;
    if (q == 0) {
        float2 es = __ldg(&g_es2[s]);
        float2 ed = __ldg(&g_ed2[t]);
        float2 sm = __ldg(&g_sm2[mn]);
        float2 sr = __ldg(&g_sr2[r]);
        ex0 = __expf(es.x + ed.x + sm.x + sr.x);
        ex1 = __expf(es.y + ed.y + sm.y + sr.y);
        red_add_v2(&g_denom2[t], ex0, ex1);
    }
    int base = lane & ~15;
    ex0 = __shfl_sync(0xffffffffu, ex0, base);
    ex1 = __shfl_sync(0xffffffffu, ex1, base);
    float ex = (q & 8) ? ex1 : ex0;
    u64 A = __ldg(&g_hph8[s * 16 + q]);
    u64 B = __ldg(&g_vmidh8[mn * 16 + q]);
    u64 C = __ldg(&g_vrelh8[r * 16 + q]);
    __half2 a01 = ((__half2*)&A)[0], a23 = ((__half2*)&A)[1];
    __half2 b01 = ((__half2*)&B)[0], b23 = ((__half2*)&B)[1];
    __half2 c01 = ((__half2*)&C)[0], c23 = ((__half2*)&C)[1];
    __half2 s01 = __hadd2(__hadd2(a01, b01), c01);
    __half2 s23 = __hadd2(__hadd2(a23, b23), c23);
    float2 f01 = __half22float2(s01);
    float2 f23 = __half22float2(s23);
    float4 v;
    v.x = ex * f01.x; v.y = ex * f01.y;
    v.z = ex * f23.x; v.w = ex * f23.y;
    red_add_v4(((float*)g_rst4) + (size_t)t * HD + q * 4, v);
}

// ---------------- final ----------------
__global__ void k_final(const float* __restrict__ b_edge, float* __restrict__ out) {
    int tid = threadIdx.x;
    int nl  = tid >> 6, c = tid & 63;
    int n   = blockIdx.x * 4 + nl;
    int hd  = c >> 5, d = c & 31;
    float den = ((const float*)&g_denom2[n])[hd];
    float rst = (den > 0.f) ? ((float*)g_rst4)[n * HD + c] / den + g_vb[c] : 0.f;
    float hpv = __half2float(((const __half*)g_hph8)[n * HD + c]);
    float val = fmaxf(rst + b_edge[d] + hpv, 0.f);
    float ss  = val * val;
#pragma unroll
    for (int o = 16; o > 0; o >>= 1) ss += __shfl_down_sync(0xffffffffu, ss, o);
    __shared__ float sp[8];
    if ((tid & 31) == 0) sp[tid >> 5] = ss;
    __syncthreads();
    float tot  = sp[nl * 2] + sp[nl * 2 + 1];
    float norm = fmaxf(sqrtf(tot), 1e-12f);
    out[n * HD + c] = val / norm;
}

extern "C" void kernel_launch(void* const* d_in, const int* in_sizes, int n_in,
                              void* d_out, int out_size) {
    const float* h         = (const float*)d_in[0];
    const float* W_t       = (const float*)d_in[1];
    const float* b_t       = (const float*)d_in[2];
    const float* nfeat_mid = (const float*)d_in[3];
    const float* W_mid     = (const float*)d_in[4];
    const float* b_mid     = (const float*)d_in[5];
    const float* efeat_rel = (const float*)d_in[6];
    const float* W_rel     = (const float*)d_in[7];
    const float* b_rel     = (const float*)d_in[8];
    const float* attn_src  = (const float*)d_in[9];
    const float* attn_dst  = (const float*)d_in[10];
    const float* attn_edge = (const float*)d_in[11];
    const float* W_edge    = (const float*)d_in[12];
    const float* b_edge    = (const float*)d_in[13];
    const int*   src_idx   = (const int*)d_in[14];
    const int*   dst_idx   = (const int*)d_in[15];
    const int*   hn        = (const int*)d_in[16];
    const int*   he        = (const int*)d_in[17];
    float* out = (float*)d_out;

    k_init_prep<<<3126, 256>>>(W_mid, W_rel, b_mid, b_rel, W_edge);
    k_proj_target<<<(NN + 31) / 32, 256>>>(h, W_t, b_t, attn_src, attn_dst);
    k_proj_mid<<<NN / 16, 128>>>(nfeat_mid, W_mid, b_mid, attn_edge);
    k_proj_rel<<<ERELN / 16, 128>>>(efeat_rel, W_rel, b_rel, attn_edge);
    k_edge_agg<<<(EE * 16) / 256, 256>>>(src_idx, dst_idx, hn, he);
    k_final<<<NN / 4, 256>>>(b_edge, out);
}

// round 9
// speedup vs baseline: 1.1879x; 1.0295x over previous
#include <cuda_runtime.h>
#include <cuda_fp16.h>

typedef unsigned long long u64;

#define NN     50000
#define EE     800000
#define HH     2
#define DD     32
#define HD     64
#define INDIM  64
#define ERELN  200000
#define DRELN  32

// ---------------- scratch ----------------
__device__ u64      g_hph8[NN * 16];       // half hp (edge gather + residual)
__device__ u64      g_vmidh8[NN * 16];
__device__ u64      g_vrelh8[ERELN * 16];
__device__ float2   g_es2[NN];
__device__ float2   g_ed2[NN];
__device__ float2   g_sm2[NN];
__device__ float2   g_sr2[ERELN];
__device__ float2   g_denom2[NN];
__device__ float4   g_rst4[NN * 16];
__device__ float    g_Mmid[INDIM * HD];
__device__ float    g_Mrel[DRELN * HD];
__device__ float    g_vb[HD];

// ---------------- helpers ----------------
__device__ __forceinline__ u64 pack2(float lo, float hi) {
    u64 r; asm("mov.b64 %0, {%1,%2};" : "=l"(r) : "f"(lo), "f"(hi)); return r;
}
__device__ __forceinline__ void unpack2(u64 v, float& lo, float& hi) {
    asm("mov.b64 {%0,%1}, %2;" : "=f"(lo), "=f"(hi) : "l"(v));
}
__device__ __forceinline__ void ffma2(u64& d, u64 a, u64 b) {
    asm("fma.rn.f32x2 %0, %1, %2, %0;" : "+l"(d) : "l"(a), "l"(b));
}
__device__ __forceinline__ u64 addf32x2(u64 a, u64 b) {
    u64 r; asm("add.rn.f32x2 %0, %1, %2;" : "=l"(r) : "l"(a), "l"(b)); return r;
}
__device__ __forceinline__ void red_add_v4(float* p, float4 v) {
    asm volatile("red.global.add.v4.f32 [%0], {%1,%2,%3,%4};"
                 :: "l"(p), "f"(v.x), "f"(v.y), "f"(v.z), "f"(v.w) : "memory");
}
__device__ __forceinline__ void red_add_v2(float2* p, float a, float b) {
    asm volatile("red.global.add.v2.f32 [%0], {%1,%2};"
                 :: "l"(p), "f"(a), "f"(b) : "memory");
}

// ---------------- init + prep ----------------
__global__ void k_init_prep(const float* __restrict__ W_mid, const float* __restrict__ W_rel,
                            const float* __restrict__ b_mid, const float* __restrict__ b_rel,
                            const float* __restrict__ We) {
    int tid = threadIdx.x;
    if (blockIdx.x == 0) {
        __shared__ float sWe[64 * 32];
        for (int i = tid; i < 2048; i += 256) sWe[i] = We[i];
        __syncthreads();
        for (int idx = tid; idx < INDIM * HD; idx += 256) {
            int k = idx >> 6, c = idx & 63, h = c >> 5, d = c & 31;
            float acc = 0.f;
            for (int dd = 0; dd < 32; dd++)
                acc = fmaf(W_mid[k * 64 + h * 32 + dd], sWe[dd * 32 + d], acc);
            g_Mmid[idx] = acc;
        }
        for (int idx = tid; idx < DRELN * HD; idx += 256) {
            int k = idx >> 6, c = idx & 63, h = c >> 5, d = c & 31;
            float acc = 0.f;
            for (int dd = 0; dd < 32; dd++)
                acc = fmaf(W_rel[k * 64 + h * 32 + dd], sWe[(32 + dd) * 32 + d], acc);
            g_Mrel[idx] = acc;
        }
        if (tid < HD) {
            int h = tid >> 5, d = tid & 31;
            float acc = 0.f;
            for (int dd = 0; dd < 32; dd++) {
                acc = fmaf(b_mid[h * 32 + dd], sWe[dd * 32 + d], acc);
                acc = fmaf(b_rel[h * 32 + dd], sWe[(32 + dd) * 32 + d], acc);
            }
            g_vb[tid] = acc;
        }
    } else {
        int i = (blockIdx.x - 1) * 256 + tid;
        if (i < NN * 16) g_rst4[i] = make_float4(0.f, 0.f, 0.f, 0.f);
        if (i < NN)      g_denom2[i] = make_float2(0.f, 0.f);
    }
}

// ---------------- target projection: K-split across warps ----------------
__global__ void __launch_bounds__(256) k_proj_target(const float* __restrict__ x,
                              const float* __restrict__ W,
                              const float* __restrict__ b,
                              const float* __restrict__ asrc,
                              const float* __restrict__ adst) {
    __shared__ float sx[32 * INDIM];
    __shared__ float spT[2][32][HD];
    int tid = threadIdx.x, w = tid >> 5, lane = tid & 31;
    int kh = w & 1, head = (w >> 1) & 1, slot = w >> 2;
    int n0 = blockIdx.x * 32;
    int nrows = min(32, NN - n0);
    for (int i = tid; i < nrows * 16; i += 256)
        ((float4*)sx)[i] = ((const float4*)(x + (size_t)n0 * INDIM))[i];
    int col = head * 32 + lane;
    float wreg[32];
#pragma unroll
    for (int kk = 0; kk < 32; kk++) wreg[kk] = W[(kh * 32 + kk) * HD + col];
    __syncthreads();
    for (int row = slot; row < nrows; row += 2) {
        float a0 = 0.f, a1 = 0.f, a2 = 0.f, a3 = 0.f;
        const float4* xrw = (const float4*)(sx + row * INDIM + kh * 32);
#pragma unroll
        for (int k4 = 0; k4 < 8; k4++) {
            float4 xv = xrw[k4];
            a0 = fmaf(xv.x, wreg[4 * k4 + 0], a0);
            a1 = fmaf(xv.y, wreg[4 * k4 + 1], a1);
            a2 = fmaf(xv.z, wreg[4 * k4 + 2], a2);
            a3 = fmaf(xv.w, wreg[4 * k4 + 3], a3);
        }
        spT[kh][row][col] = (a0 + a1) + (a2 + a3);
    }
    __syncthreads();
    if (kh == 0) {
        float bb = b[col];
        float as = asrc[col], ad = adst[col];
        __half* hph = (__half*)g_hph8;
        for (int row = slot; row < nrows; row += 2) {
            int n = n0 + row;
            float acc = spT[0][row][col] + spT[1][row][col] + bb;
            hph[n * HD + col] = __float2half_rn(acc);
            float r = fmaxf(acc, 0.f);
            float vs = r * as, vd = r * ad;
#pragma unroll
            for (int o = 16; o > 0; o >>= 1) {
                vs += __shfl_down_sync(0xffffffffu, vs, o);
                vd += __shfl_down_sync(0xffffffffu, vd, o);
            }
            if (lane == 0) {
                ((float*)&g_es2[n])[head] = vs;
                ((float*)&g_ed2[n])[head] = vd;
            }
        }
    }
}

// ---------------- mid projection: paired-rows FFMA2, K split 4 ways, LDS.128 ----------------
// 256 thr = 8 warps: kh = w&3 (16 K each), head = w>>2; 16 rows (8 pairs)/block
__global__ void __launch_bounds__(256) k_proj_mid(const float* __restrict__ x,
                           const float* __restrict__ W,
                           const float* __restrict__ b,
                           const float* __restrict__ aedge) {
    __shared__ __align__(16) u64 spx[8][INDIM];   // (xA,xB) pairs, 4KB
    __shared__ __align__(16) u64 spW[4][8][64];   // 16KB
    __shared__ __align__(16) u64 spM[4][8][64];   // 16KB
    int tid = threadIdx.x, w = tid >> 5, lane = tid & 31;
    int kh = w & 3, head = w >> 2;
    int n0 = blockIdx.x * 16;
    {   // stage 16 rows x 64 floats as interleaved row pairs
        int row = tid >> 4, k4 = tid & 15;
        float4 v = ((const float4*)(x + (size_t)(n0 + row) * INDIM))[k4];
        int pair = row >> 1, sub = row & 1;
        float* bp = (float*)&spx[pair][k4 * 4];
        bp[0 + sub] = v.x; bp[2 + sub] = v.y;
        bp[4 + sub] = v.z; bp[6 + sub] = v.w;
    }
    int col = head * 32 + lane;
    u64 wdup[16], mdup[16];
#pragma unroll
    for (int kk = 0; kk < 16; kk++) {
        int k = kh * 16 + kk;
        float wv = W[k * HD + col];
        float mv = g_Mmid[k * HD + col];
        wdup[kk] = pack2(wv, wv);
        mdup[kk] = pack2(mv, mv);
    }
    __syncthreads();
#pragma unroll
    for (int p0 = 0; p0 < 4; p0++) {
        u64 dW0 = 0, dM0 = 0, dW1 = 0, dM1 = 0;
        const ulonglong2* xa = (const ulonglong2*)&spx[p0][kh * 16];
        const ulonglong2* xb = (const ulonglong2*)&spx[p0 + 4][kh * 16];
#pragma unroll
        for (int k2 = 0; k2 < 8; k2++) {
            ulonglong2 sa = xa[k2], sb = xb[k2];
            ffma2(dW0, sa.x, wdup[2 * k2 + 0]);
            ffma2(dM0, sa.x, mdup[2 * k2 + 0]);
            ffma2(dW1, sb.x, wdup[2 * k2 + 0]);
            ffma2(dM1, sb.x, mdup[2 * k2 + 0]);
            ffma2(dW0, sa.y, wdup[2 * k2 + 1]);
            ffma2(dM0, sa.y, mdup[2 * k2 + 1]);
            ffma2(dW1, sb.y, wdup[2 * k2 + 1]);
            ffma2(dM1, sb.y, mdup[2 * k2 + 1]);
        }
        spW[kh][p0][col] = dW0;  spM[kh][p0][col] = dM0;
        spW[kh][p0 + 4][col] = dW1;  spM[kh][p0 + 4][col] = dM1;
    }
    __syncthreads();
    if (kh == 0) {
        float bb = b[col];
        float av = aedge[head * 64 + lane];
        __half* vm = (__half*)g_vmidh8;
#pragma unroll
        for (int p = 0; p < 8; p++) {
            u64 uW = addf32x2(addf32x2(spW[0][p][col], spW[1][p][col]),
                              addf32x2(spW[2][p][col], spW[3][p][col]));
            u64 uM = addf32x2(addf32x2(spM[0][p][col], spM[1][p][col]),
                              addf32x2(spM[2][p][col], spM[3][p][col]));
            float aA, aB, vA, vB;
            unpack2(uW, aA, aB); unpack2(uM, vA, vB);
            aA += bb; aB += bb;
            int nA = n0 + 2 * p, nB = nA + 1;
            vm[nA * HD + col] = __float2half_rn(vA);
            vm[nB * HD + col] = __float2half_rn(vB);
            float sA = fmaxf(aA, 0.f) * av;
            float sB = fmaxf(aB, 0.f) * av;
#pragma unroll
            for (int o = 16; o > 0; o >>= 1) {
                sA += __shfl_down_sync(0xffffffffu, sA, o);
                sB += __shfl_down_sync(0xffffffffu, sB, o);
            }
            if (lane == 0) {
                ((float*)&g_sm2[nA])[head] = sA;
                ((float*)&g_sm2[nB])[head] = sB;
            }
        }
    }
}

// ---------------- rel projection: paired-rows FFMA2, K split 2 ways, LDS.128 ----------------
__global__ void __launch_bounds__(128) k_proj_rel(const float* __restrict__ x,
                           const float* __restrict__ W,
                           const float* __restrict__ b,
                           const float* __restrict__ aedge) {
    __shared__ __align__(16) u64 spx[8][DRELN];
    __shared__ __align__(16) u64 spW[2][8][64];
    __shared__ __align__(16) u64 spM[2][8][64];
    int tid = threadIdx.x, w = tid >> 5, lane = tid & 31;
    int kh = w & 1, head = w >> 1;
    int n0 = blockIdx.x * 16;
    {
        int row = tid >> 3, k4 = tid & 7;
        float4 v = ((const float4*)(x + (size_t)(n0 + row) * DRELN))[k4];
        int pair = row >> 1, sub = row & 1;
        float* bp = (float*)&spx[pair][k4 * 4];
        bp[0 + sub] = v.x; bp[2 + sub] = v.y;
        bp[4 + sub] = v.z; bp[6 + sub] = v.w;
    }
    int col = head * 32 + lane;
    u64 wdup[16], mdup[16];
#pragma unroll
    for (int kk = 0; kk < 16; kk++) {
        int k = kh * 16 + kk;
        float wv = W[k * HD + col];
        float mv = g_Mrel[k * HD + col];
        wdup[kk] = pack2(wv, wv);
        mdup[kk] = pack2(mv, mv);
    }
    __syncthreads();
#pragma unroll
    for (int p0 = 0; p0 < 4; p0++) {
        u64 dW0 = 0, dM0 = 0, dW1 = 0, dM1 = 0;
        const ulonglong2* xa = (const ulonglong2*)&spx[p0][kh * 16];
        const ulonglong2* xb = (const ulonglong2*)&spx[p0 + 4][kh * 16];
#pragma unroll
        for (int k2 = 0; k2 < 8; k2++) {
            ulonglong2 sa = xa[k2], sb = xb[k2];
            ffma2(dW0, sa.x, wdup[2 * k2 + 0]);
            ffma2(dM0, sa.x, mdup[2 * k2 + 0]);
            ffma2(dW1, sb.x, wdup[2 * k2 + 0]);
            ffma2(dM1, sb.x, mdup[2 * k2 + 0]);
            ffma2(dW0, sa.y, wdup[2 * k2 + 1]);
            ffma2(dM0, sa.y, mdup[2 * k2 + 1]);
            ffma2(dW1, sb.y, wdup[2 * k2 + 1]);
            ffma2(dM1, sb.y, mdup[2 * k2 + 1]);
        }
        spW[kh][p0][col] = dW0;  spM[kh][p0][col] = dM0;
        spW[kh][p0 + 4][col] = dW1;  spM[kh][p0 + 4][col] = dM1;
    }
    __syncthreads();
    if (kh == 0) {
        float bb = b[col];
        float av = aedge[head * 64 + 32 + lane];
        __half* vr = (__half*)g_vrelh8;
#pragma unroll
        for (int p = 0; p < 8; p++) {
            u64 uW = addf32x2(spW[0][p][col], spW[1][p][col]);
            u64 uM = addf32x2(spM[0][p][col], spM[1][p][col]);
            float aA, aB, vA, vB;
            unpack2(uW, aA, aB); unpack2(uM, vA, vB);
            aA += bb; aB += bb;
            int nA = n0 + 2 * p, nB = nA + 1;
            vr[nA * HD + col] = __float2half_rn(vA);
            vr[nB * HD + col] = __float2half_rn(vB);
            float sA = fmaxf(aA, 0.f) * av;
            float sB = fmaxf(aB, 0.f) * av;
#pragma unroll
            for (int o = 16; o > 0; o >>= 1) {
                sA += __shfl_down_sync(0xffffffffu, sA, o);
                sB += __shfl_down_sync(0xffffffffu, sB, o);
            }
            if (lane == 0) {
                ((float*)&g_sr2[nA])[head] = sA;
                ((float*)&g_sr2[nB])[head] = sB;
            }
        }
    }
}

// ---------------- fused edge pass (fp16 gathers) ----------------
__global__ void k_edge_agg(const int* __restrict__ src, const int* __restrict__ dst,
                           const int* __restrict__ hn,  const int* __restrict__ he) {
    int gt = blockIdx.x * 256 + threadIdx.x;
    int e = gt >> 4;
    int q = gt & 15;
    int lane = threadIdx.x & 31;
    int s = src[e], t = dst[e], mn = hn[e], r = he[e];
    float ex0 = 0.f, ex1 = 0.f;
    if (q == 0) {
        float2 es = __ldg(&g_es2[s]);
        float2 ed = __ldg(&g_ed2[t]);
        float2 sm = __ldg(&g_sm2[mn]);
        float2 sr = __ldg(&g_sr2[r]);
        ex0 = __expf(es.x + ed.x + sm.x + sr.x);
        ex1 = __expf(es.y + ed.y + sm.y + sr.y);
        red_add_v2(&g_denom2[t], ex0, ex1);
    }
    int base = lane & ~15;
    ex0 = __shfl_sync(0xffffffffu, ex0, base);
    ex1 = __shfl_sync(0xffffffffu, ex1, base);
    float ex = (q & 8) ? ex1 : ex0;
    u64 A = __ldg(&g_hph8[s * 16 + q]);
    u64 B = __ldg(&g_vmidh8[mn * 16 + q]);
    u64 C = __ldg(&g_vrelh8[r * 16 + q]);
    __half2 a01 = ((__half2*)&A)[0], a23 = ((__half2*)&A)[1];
    __half2 b01 = ((__half2*)&B)[0], b23 = ((__half2*)&B)[1];
    __half2 c01 = ((__half2*)&C)[0], c23 = ((__half2*)&C)[1];
    __half2 s01 = __hadd2(__hadd2(a01, b01), c01);
    __half2 s23 = __hadd2(__hadd2(a23, b23), c23);
    float2 f01 = __half22float2(s01);
    float2 f23 = __half22float2(s23);
    float4 v;
    v.x = ex * f01.x; v.y = ex * f01.y;
    v.z = ex * f23.x; v.w = ex * f23.y;
    red_add_v4(((float*)g_rst4) + (size_t)t * HD + q * 4, v);
}

// ---------------- final: float4/thread, 16 nodes/block, shfl-only reduction ----------------
__global__ void __launch_bounds__(256) k_final(const float* __restrict__ b_edge,
                                               float* __restrict__ out) {
    int tid = threadIdx.x;
    int nl = tid >> 4, q = tid & 15;
    int n = blockIdx.x * 16 + nl;
    int hd = q >> 3;
    float den = ((const float*)&g_denom2[n])[hd];
    float inv = (den > 0.f) ? 1.f / den : 0.f;
    float vbm = (den > 0.f) ? 1.f : 0.f;
    float4 rv = g_rst4[n * 16 + q];
    float4 vbq = ((const float4*)g_vb)[q];
    float4 be = ((const float4*)b_edge)[q & 7];
    u64 A = g_hph8[n * 16 + q];
    __half2 a01 = ((__half2*)&A)[0], a23 = ((__half2*)&A)[1];
    float2 h01 = __half22float2(a01);
    float2 h23 = __half22float2(a23);
    float4 val;
    val.x = fmaxf(fmaf(rv.x, inv, vbq.x * vbm) + be.x + h01.x, 0.f);
    val.y = fmaxf(fmaf(rv.y, inv, vbq.y * vbm) + be.y + h01.y, 0.f);
    val.z = fmaxf(fmaf(rv.z, inv, vbq.z * vbm) + be.z + h23.x, 0.f);
    val.w = fmaxf(fmaf(rv.w, inv, vbq.w * vbm) + be.w + h23.y, 0.f);
    float ss = val.x * val.x + val.y * val.y + val.z * val.z + val.w * val.w;
#pragma unroll
    for (int o = 8; o > 0; o >>= 1) ss += __shfl_xor_sync(0xffffffffu, ss, o, 16);
    float norm = fmaxf(sqrtf(ss), 1e-12f);
    float rn = 1.f / norm;
    float4 o4;
    o4.x = val.x * rn; o4.y = val.y * rn; o4.z = val.z * rn; o4.w = val.w * rn;
    ((float4*)out)[n * 16 + q] = o4;
}

extern "C" void kernel_launch(void* const* d_in, const int* in_sizes, int n_in,
                              void* d_out, int out_size) {
    const float* h         = (const float*)d_in[0];
    const float* W_t       = (const float*)d_in[1];
    const float* b_t       = (const float*)d_in[2];
    const float* nfeat_mid = (const float*)d_in[3];
    const float* W_mid     = (const float*)d_in[4];
    const float* b_mid     = (const float*)d_in[5];
    const float* efeat_rel = (const float*)d_in[6];
    const float* W_rel     = (const float*)d_in[7];
    const float* b_rel     = (const float*)d_in[8];
    const float* attn_src  = (const float*)d_in[9];
    const float* attn_dst  = (const float*)d_in[10];
    const float* attn_edge = (const float*)d_in[11];
    const float* W_edge    = (const float*)d_in[12];
    const float* b_edge    = (const float*)d_in[13];
    const int*   src_idx   = (const int*)d_in[14];
    const int*   dst_idx   = (const int*)d_in[15];
    const int*   hn        = (const int*)d_in[16];
    const int*   he        = (const int*)d_in[17];
    float* out = (float*)d_out;

    k_init_prep<<<3126, 256>>>(W_mid, W_rel, b_mid, b_rel, W_edge);
    k_proj_target<<<(NN + 31) / 32, 256>>>(h, W_t, b_t, attn_src, attn_dst);
    k_proj_mid<<<NN / 16, 256>>>(nfeat_mid, W_mid, b_mid, attn_edge);
    k_proj_rel<<<ERELN / 16, 128>>>(efeat_rel, W_rel, b_rel, attn_edge);
    k_edge_agg<<<(EE * 16) / 256, 256>>>(src_idx, dst_idx, hn, he);
    k_final<<<NN / 16, 256>>>(b_edge, out);
}